// round 5
// baseline (speedup 1.0000x reference)
#include <cuda_runtime.h>

#define B_ 32
#define C_ 256
#define P_ 32
#define HW_ 3136
#define NCHUNK 14
#define TILES_PER_BLOCK 7
#define HWT 32
#define CHUNK_HW (TILES_PER_BLOCK * HWT)   // 224; 14*224 = 3136 exactly

// Partial results: scratch[chunk][b][p][c]
__device__ float g_scratch[NCHUNK * B_ * P_ * C_];

__global__ __launch_bounds__(256) void rfe_main(const float* __restrict__ x,
                                                const float* __restrict__ part,
                                                const float* __restrict__ cw,
                                                const float* __restrict__ cbp) {
    // x_s: [k][c], row stride 257 (conflict-free transpose)
    __shared__ float x_s[HWT * 257];
    // w_s: raw part tile, [k][p], row stride 36 (rows 16B-aligned for LDS.128)
    __shared__ float w_s[HWT * 36];
    __shared__ float att_s[HWT];
    __shared__ float cw_s[P_];

    const int tid  = threadIdx.x;
    const int lane = tid & 31;
    const int warp = tid >> 5;
    const int b     = blockIdx.y;
    const int chunk = blockIdx.x;

    if (tid < P_) cw_s[tid] = cw[tid];
    const float cb = cbp[0];

    const float* xb = x    + (size_t)b * C_ * HW_;
    const float* pb = part + (size_t)b * P_ * HW_;

    // 16 f32x2 accumulators = feats[{2j, 2j+1}, c_own]
    unsigned long long acc[16];
#pragma unroll
    for (int j = 0; j < 16; ++j) acc[j] = 0ULL;

    const int c_own = tid;  // each thread owns one channel

#pragma unroll 1
    for (int t = 0; t < TILES_PER_BLOCK; ++t) {
        const int base = chunk * CHUNK_HW + t * HWT;

        // ---- load part tile [32p x 32k] -> w_s[k][p] ----
        {
            const int p  = tid >> 3;
            const int k4 = (tid & 7) * 4;
            float4 v = *(const float4*)(pb + (size_t)p * HW_ + base + k4);
            w_s[(k4 + 0) * 36 + p] = v.x;
            w_s[(k4 + 1) * 36 + p] = v.y;
            w_s[(k4 + 2) * 36 + p] = v.z;
            w_s[(k4 + 3) * 36 + p] = v.w;
        }
        // ---- load x tile [256c x 32k] -> x_s[k][c] (transposed) ----
        {
            const int k4 = (lane & 7) * 4;
            const int r  = lane >> 3;
#pragma unroll
            for (int i = 0; i < 8; ++i) {
                const int c = warp * 32 + i * 4 + r;
                float4 v = *(const float4*)(xb + (size_t)c * HW_ + base + k4);
                x_s[(k4 + 0) * 257 + c] = v.x;
                x_s[(k4 + 1) * 257 + c] = v.y;
                x_s[(k4 + 2) * 257 + c] = v.z;
                x_s[(k4 + 3) * 257 + c] = v.w;
            }
        }
        __syncthreads();

        // ---- attention for this tile (warp 0: one lane per pixel) ----
        if (tid < HWT) {
            float s = cb;
#pragma unroll
            for (int p = 0; p < P_; ++p) s += w_s[tid * 36 + p] * cw_s[p];
            att_s[tid] = 1.0f / (1.0f + __expf(-s));
        }
        __syncthreads();

        // ---- GEMM accumulation: acc[p-pair] += part[k][p-pair] * (x[k][c]*att[k]) ----
#pragma unroll 8
        for (int k = 0; k < HWT; ++k) {
            const float xa = x_s[k * 257 + c_own] * att_s[k];
            unsigned long long xx;
            asm("mov.b64 %0, {%1, %1};" : "=l"(xx) : "f"(xa));
            const uint4* wrow = (const uint4*)(w_s + k * 36);
#pragma unroll
            for (int j4 = 0; j4 < 8; ++j4) {
                uint4 w4 = wrow[j4];   // broadcast LDS.128 across the warp
                unsigned long long w01, w23;
                asm("mov.b64 %0, {%1, %2};" : "=l"(w01) : "r"(w4.x), "r"(w4.y));
                asm("mov.b64 %0, {%1, %2};" : "=l"(w23) : "r"(w4.z), "r"(w4.w));
                asm("fma.rn.f32x2 %0, %1, %2, %0;" : "+l"(acc[2 * j4 + 0]) : "l"(w01), "l"(xx));
                asm("fma.rn.f32x2 %0, %1, %2, %0;" : "+l"(acc[2 * j4 + 1]) : "l"(w23), "l"(xx));
            }
        }
        __syncthreads();
    }

    // ---- write partials: scratch[chunk][b][p][c] ----
    float* outp = g_scratch + ((size_t)chunk * B_ + b) * P_ * C_;
#pragma unroll
    for (int j = 0; j < 16; ++j) {
        float f0, f1;
        asm("mov.b64 {%0, %1}, %2;" : "=f"(f0), "=f"(f1) : "l"(acc[j]));
        outp[(2 * j + 0) * C_ + c_own] = f0;
        outp[(2 * j + 1) * C_ + c_own] = f1;
    }
}

__global__ __launch_bounds__(256) void rfe_reduce(float* __restrict__ out) {
    const int idx = blockIdx.x * blockDim.x + threadIdx.x;  // B*P*C = 262144 threads
    float s = 0.0f;
#pragma unroll
    for (int ch = 0; ch < NCHUNK; ++ch)
        s += g_scratch[(size_t)ch * (B_ * P_ * C_) + idx];
    out[idx] = s;
}

extern "C" void kernel_launch(void* const* d_in, const int* in_sizes, int n_in,
                              void* d_out, int out_size) {
    const float* x    = (const float*)d_in[0];
    const float* part = (const float*)d_in[1];
    const float* cw   = (const float*)d_in[2];
    const float* cb   = (const float*)d_in[3];
    float* out = (float*)d_out;

    dim3 grid(NCHUNK, B_);
    rfe_main<<<grid, 256>>>(x, part, cw, cb);
    rfe_reduce<<<(B_ * P_ * C_) / 256, 256>>>(out);
}

// round 6
// speedup vs baseline: 1.0240x; 1.0240x over previous
#include <cuda_runtime.h>

#define B_ 32
#define C_ 256
#define P_ 32
#define HW_ 3136
#define NCHUNK 14
#define TILES_PER_BLOCK 7
#define HWT 32
#define CHUNK_HW (TILES_PER_BLOCK * HWT)   // 224; 14*224 = 3136 exactly

// Partial results: scratch[chunk][b][p][c]
__device__ float g_scratch[NCHUNK * B_ * P_ * C_];

__global__ __launch_bounds__(256) void rfe_main(const float* __restrict__ x,
                                                const float* __restrict__ part,
                                                const float* __restrict__ cw,
                                                const float* __restrict__ cbp) {
    // x_s: [k][c], row stride 257 (conflict-free transpose)
    __shared__ float x_s[HWT * 257];
    // w_s: raw part tile, [k][p], row stride 36 (rows 16B-aligned for LDS.128)
    __shared__ float w_s[HWT * 36];
    __shared__ float att_s[HWT];
    __shared__ float cw_s[P_];

    const int tid  = threadIdx.x;
    const int lane = tid & 31;
    const int warp = tid >> 5;
    const int b     = blockIdx.y;
    const int chunk = blockIdx.x;

    if (tid < P_) cw_s[tid] = cw[tid];
    const float cb = cbp[0];

    const float* xb = x    + (size_t)b * C_ * HW_;
    const float* pb = part + (size_t)b * P_ * HW_;

    // 16 f32x2 accumulators = feats[{2j, 2j+1}, c_own]
    unsigned long long acc[16];
#pragma unroll
    for (int j = 0; j < 16; ++j) acc[j] = 0ULL;

    const int c_own = tid;  // each thread owns one channel

#pragma unroll 1
    for (int t = 0; t < TILES_PER_BLOCK; ++t) {
        const int base = chunk * CHUNK_HW + t * HWT;

        // ---- load part tile [32p x 32k] -> w_s[k][p] ----
        {
            const int p  = tid >> 3;
            const int k4 = (tid & 7) * 4;
            float4 v = *(const float4*)(pb + (size_t)p * HW_ + base + k4);
            w_s[(k4 + 0) * 36 + p] = v.x;
            w_s[(k4 + 1) * 36 + p] = v.y;
            w_s[(k4 + 2) * 36 + p] = v.z;
            w_s[(k4 + 3) * 36 + p] = v.w;
        }
        // ---- load x tile [256c x 32k] -> x_s[k][c] (transposed) ----
        {
            const int k4 = (lane & 7) * 4;
            const int r  = lane >> 3;
#pragma unroll
            for (int i = 0; i < 8; ++i) {
                const int c = warp * 32 + i * 4 + r;
                float4 v = *(const float4*)(xb + (size_t)c * HW_ + base + k4);
                x_s[(k4 + 0) * 257 + c] = v.x;
                x_s[(k4 + 1) * 257 + c] = v.y;
                x_s[(k4 + 2) * 257 + c] = v.z;
                x_s[(k4 + 3) * 257 + c] = v.w;
            }
        }
        __syncthreads();

        // ---- attention for this tile (warp 0: one lane per pixel) ----
        if (tid < HWT) {
            float s = cb;
#pragma unroll
            for (int p = 0; p < P_; ++p) s += w_s[tid * 36 + p] * cw_s[p];
            att_s[tid] = 1.0f / (1.0f + __expf(-s));
        }
        __syncthreads();

        // ---- GEMM accumulation: acc[p-pair] += part[k][p-pair] * (x[k][c]*att[k]) ----
#pragma unroll 8
        for (int k = 0; k < HWT; ++k) {
            const float xa = x_s[k * 257 + c_own] * att_s[k];
            unsigned long long xx;
            asm("mov.b64 %0, {%1, %1};" : "=l"(xx) : "f"(xa));
            const uint4* wrow = (const uint4*)(w_s + k * 36);
#pragma unroll
            for (int j4 = 0; j4 < 8; ++j4) {
                uint4 w4 = wrow[j4];   // broadcast LDS.128 across the warp
                unsigned long long w01, w23;
                asm("mov.b64 %0, {%1, %2};" : "=l"(w01) : "r"(w4.x), "r"(w4.y));
                asm("mov.b64 %0, {%1, %2};" : "=l"(w23) : "r"(w4.z), "r"(w4.w));
                asm("fma.rn.f32x2 %0, %1, %2, %0;" : "+l"(acc[2 * j4 + 0]) : "l"(w01), "l"(xx));
                asm("fma.rn.f32x2 %0, %1, %2, %0;" : "+l"(acc[2 * j4 + 1]) : "l"(w23), "l"(xx));
            }
        }
        __syncthreads();
    }

    // ---- write partials: scratch[chunk][b][p][c] ----
    float* outp = g_scratch + ((size_t)chunk * B_ + b) * P_ * C_;
#pragma unroll
    for (int j = 0; j < 16; ++j) {
        float f0, f1;
        asm("mov.b64 {%0, %1}, %2;" : "=f"(f0), "=f"(f1) : "l"(acc[j]));
        outp[(2 * j + 0) * C_ + c_own] = f0;
        outp[(2 * j + 1) * C_ + c_own] = f1;
    }
}

__global__ __launch_bounds__(256) void rfe_reduce(float* __restrict__ out) {
    const int idx = blockIdx.x * blockDim.x + threadIdx.x;  // B*P*C = 262144 threads
    float s = 0.0f;
#pragma unroll
    for (int ch = 0; ch < NCHUNK; ++ch)
        s += g_scratch[(size_t)ch * (B_ * P_ * C_) + idx];
    out[idx] = s;
}

extern "C" void kernel_launch(void* const* d_in, const int* in_sizes, int n_in,
                              void* d_out, int out_size) {
    const float* x    = (const float*)d_in[0];
    const float* part = (const float*)d_in[1];
    const float* cw   = (const float*)d_in[2];
    const float* cb   = (const float*)d_in[3];
    float* out = (float*)d_out;

    dim3 grid(NCHUNK, B_);
    rfe_main<<<grid, 256>>>(x, part, cw, cb);
    rfe_reduce<<<(B_ * P_ * C_) / 256, 256>>>(out);
}